// round 3
// baseline (speedup 1.0000x reference)
#include <cuda_runtime.h>
#include <math.h>

#define BATCH 32768
typedef unsigned long long ull;

// 128 MB inter-stage scratch: pooled conv2 output = flattened FC input:
// g_p2[sample*1024 + oc*16 + pooledpos]
__device__ float g_p2[BATCH * 1024];

// ---------------------------------------------------------------------------
// f32x2 packed-math helpers (FFMA2: 2 MACs/lane/issue, PTX-only per quickref)
// ---------------------------------------------------------------------------
__device__ __forceinline__ ull fma2(ull a, ull b, ull c) {
    ull d; asm("fma.rn.f32x2 %0, %1, %2, %3;" : "=l"(d) : "l"(a), "l"(b), "l"(c));
    return d;
}
__device__ __forceinline__ ull pack2(float lo, float hi) {
    ull d; asm("mov.b64 %0, {%1, %2};" : "=l"(d) : "f"(lo), "f"(hi));
    return d;
}
__device__ __forceinline__ float2 unpack2(ull a) {
    float2 r; asm("mov.b64 {%0, %1}, %2;" : "=f"(r.x), "=f"(r.y) : "l"(a));
    return r;
}

// ---------------------------------------------------------------------------
// Kernel A: conv1(1->32,k3,pad1)+ReLU+pool2 -> conv2(32->64,k3,pad1)+ReLU+pool2
// 4 samples per block, 256 threads. conv2 runs FFMA2 paired over ic.
// p1t layout: [sample][pos 0..33][ic 0..31], pos 0/33 are zero pads.
// ---------------------------------------------------------------------------
__global__ void __launch_bounds__(256) conv_kernel(
    const float* __restrict__ x,
    const float* __restrict__ w1, const float* __restrict__ b1,
    const float* __restrict__ w2, const float* __restrict__ b2)
{
    __shared__ float xs[4][66];                 // [s][0]=pad, [1..64]=x, [65]=pad
    __shared__ __align__(8) float p1t[4][1088]; // pos*32 + ic (transposed!)
    __shared__ float w1s[96];
    __shared__ float b1s[32];
    __shared__ float w2s[64 * 97];              // oc*97 + ic*3 + t (conflict-free)
    __shared__ float b2s[64];

    const int tid = threadIdx.x;
    const int s0  = blockIdx.x * 4;

    // ---- stage weights ----
    for (int i = tid; i < 96; i += 256) w1s[i] = w1[i];
    if (tid < 32) b1s[tid] = b1[tid];
    if (tid < 64) b2s[tid] = b2[tid];
    for (int i = tid; i < 64 * 96; i += 256) {
        int oc = i / 96, r = i % 96;
        w2s[oc * 97 + r] = w2[i];
    }
    // ---- stage input ----
    {
        int s = tid >> 6, i = tid & 63;
        xs[s][1 + i] = x[(size_t)(s0 + s) * 64 + i];
    }
    if (tid < 4)      xs[tid][0]      = 0.f;
    else if (tid < 8) xs[tid - 4][65] = 0.f;
    __syncthreads();

    // ---- phase 1: conv1 + relu + pool (writes transposed) ----
    {
        const int s    = tid >> 6;      // sample 0..3
        const int sub  = tid & 63;
        const int c    = sub & 31;      // channel: warp covers c 0..31 -> STS conflict-free
        const int half = sub >> 5;      // which 16 pooled positions
        float ww0 = w1s[c * 3 + 0], ww1 = w1s[c * 3 + 1], ww2 = w1s[c * 3 + 2];
        float bb  = b1s[c];
        float* pb = &p1t[s][0];
        if (half == 0) pb[c] = 0.f; else pb[33 * 32 + c] = 0.f;
        const int jb = half * 16;
        #pragma unroll
        for (int j = 0; j < 16; j++) {
            int i0 = 2 * (jb + j);
            float a = xs[s][i0], b = xs[s][i0 + 1], cc = xs[s][i0 + 2], d = xs[s][i0 + 3];
            float o0 = bb + ww0 * a + ww1 * b  + ww2 * cc;
            float o1 = bb + ww0 * b + ww1 * cc + ww2 * d;
            pb[(1 + jb + j) * 32 + c] = fmaxf(fmaxf(o0, o1), 0.f);
        }
    }
    __syncthreads();

    // ---- phase 2: conv2 + relu + pool, FFMA2 over ic pairs ----
    {
        const int oc = tid & 63;
        const int s  = tid >> 6;        // warp-constant -> all p1t reads broadcast
        ull acc2[32];
        #pragma unroll
        for (int p = 0; p < 32; p++) acc2[p] = 0ull;

        const float* wrow = &w2s[oc * 97];
        const ull*   pt   = (const ull*)&p1t[s][0];   // element = ic-pair

        #pragma unroll 1
        for (int ip = 0; ip < 16; ip++) {
            // weight pairs (ic=2ip lane lo, ic=2ip+1 lane hi), hoisted
            ull u0 = pack2(wrow[6 * ip + 0], wrow[6 * ip + 3]);
            ull u1 = pack2(wrow[6 * ip + 1], wrow[6 * ip + 4]);
            ull u2 = pack2(wrow[6 * ip + 2], wrow[6 * ip + 5]);
            const ull* base = pt + ip;                // base[q*16] = pos q, this ic-pair
            ull d0 = base[0], d1 = base[16];
            #pragma unroll
            for (int p = 0; p < 32; p++) {
                ull d2 = base[(p + 2) * 16];
                acc2[p] = fma2(u0, d0, acc2[p]);
                acc2[p] = fma2(u1, d1, acc2[p]);
                acc2[p] = fma2(u2, d2, acc2[p]);
                d0 = d1; d1 = d2;
            }
        }

        const float bb = b2s[oc];
        float o[16];
        #pragma unroll
        for (int j = 0; j < 16; j++) {
            float2 e = unpack2(acc2[2 * j]);
            float2 f = unpack2(acc2[2 * j + 1]);
            float a0 = e.x + e.y;       // reduce ic lanes
            float a1 = f.x + f.y;
            o[j] = fmaxf(fmaxf(a0, a1) + bb, 0.f);
        }

        float4* dst = (float4*)&g_p2[(size_t)(s0 + s) * 1024 + oc * 16];
        #pragma unroll
        for (int j = 0; j < 4; j++)
            dst[j] = make_float4(o[4 * j], o[4 * j + 1], o[4 * j + 2], o[4 * j + 3]);
    }
}

// ---------------------------------------------------------------------------
// Quantum helpers: 16-amplitude statevector in registers.
// wire w <-> bit (8 >> w) of the flat index.
// ---------------------------------------------------------------------------
__device__ __forceinline__ void apply_ry(float st[16], float c, float s, const int bit) {
    #pragma unroll
    for (int i = 0; i < 16; i++) {
        if (i & bit) continue;
        float a0 = st[i], a1 = st[i | bit];
        st[i]       = c * a0 - s * a1;
        st[i | bit] = s * a0 + c * a1;
    }
}
__device__ __forceinline__ void apply_cnot(float st[16], const int cbit, const int tbit) {
    #pragma unroll
    for (int i = 0; i < 16; i++) {
        if ((i & cbit) && !(i & tbit)) {
            float t = st[i]; st[i] = st[i | tbit]; st[i | tbit] = t;
        }
    }
}

// ---------------------------------------------------------------------------
// Kernel B: FC GEMM (M=32768, K=1024, N=64), FFMA2, M-tile 256, 256 threads,
// thread tile 8(M) x 8(N) as 8x4 f32x2 pairs. Fused pre/tanh/quantum/post head.
// ---------------------------------------------------------------------------
__global__ void __launch_bounds__(256) fc_quantum_kernel(
    const float* __restrict__ fc_w,  const float* __restrict__ fc_b,
    const float* __restrict__ pre_w, const float* __restrict__ pre_b,
    const float* __restrict__ q_params,
    const float* __restrict__ post_w, const float* __restrict__ post_b,
    float* __restrict__ out)
{
    // pool: GEMM phase = Ast(32KB dup-pairs) + Bs(4KB); epilogue = hs(33.3KB)
    __shared__ __align__(16) unsigned char pool[36864];
    __shared__ float qc[24], qs[24];    // cos/sin of fixed layer half-angles
    __shared__ float pws[256];          // pre_w (64,4)
    __shared__ float fbs[64];

    ull   (*Ast)[256] = (ull  (*)[256])(pool);          // [k][m] pairs (a,a)
    float (*Bs )[64]  = (float(*)[64]) (pool + 32768);  // [k][n]
    float (*hs )[65]  = (float(*)[65]) (pool);          // [row 0..127][n]

    const int tid = threadIdx.x;
    const int m0  = blockIdx.x * 256;
    const int tm  = tid & 31;           // m lane: rows m = tm + 32*i
    const int tn  = tid >> 5;           // n group: cols n = tn*8 .. tn*8+7

    if (tid < 24) { float h = 0.5f * q_params[tid]; qc[tid] = cosf(h); qs[tid] = sinf(h); }
    if (tid < 64) fbs[tid] = fc_b[tid];
    pws[tid] = pre_w[tid];

    ull acc2[8][4];
    #pragma unroll
    for (int i = 0; i < 8; i++)
        #pragma unroll
        for (int j = 0; j < 4; j++) acc2[i][j] = 0ull;

    const int kbB = tid >> 4;           // B stage: k row 0..15
    const int nbB = (tid & 15) * 4;     // B stage: n col (float4)

    for (int k0 = 0; k0 < 1024; k0 += 16) {
        // stage A as duplicated pairs: Ast[k][m] = (a, a)
        const float4* src = (const float4*)&g_p2[(size_t)(m0 + tid) * 1024 + k0];
        #pragma unroll
        for (int q = 0; q < 4; q++) {
            float4 v = src[q];
            Ast[4 * q + 0][tid] = pack2(v.x, v.x);
            Ast[4 * q + 1][tid] = pack2(v.y, v.y);
            Ast[4 * q + 2][tid] = pack2(v.z, v.z);
            Ast[4 * q + 3][tid] = pack2(v.w, v.w);
        }
        *(float4*)&Bs[kbB][nbB] = *(const float4*)&fc_w[(size_t)(k0 + kbB) * 64 + nbB];
        __syncthreads();

        #pragma unroll
        for (int kk = 0; kk < 16; kk++) {
            ull bp[4], ap[8];
            #pragma unroll
            for (int j = 0; j < 4; j++)
                bp[j] = *(const ull*)&Bs[kk][tn * 8 + 2 * j];   // broadcast LDS.64
            #pragma unroll
            for (int i = 0; i < 8; i++)
                ap[i] = Ast[kk][tm + 32 * i];                    // conflict-free LDS.64
            #pragma unroll
            for (int i = 0; i < 8; i++)
                #pragma unroll
                for (int j = 0; j < 4; j++)
                    acc2[i][j] = fma2(ap[i], bp[j], acc2[i][j]);
        }
        __syncthreads();
    }

    // ---- epilogue in two 128-row halves (hs reuses Ast/Bs pool) ----
    for (int h = 0; h < 2; h++) {
        #pragma unroll
        for (int i = 0; i < 4; i++) {
            const int r = tm + 32 * i;          // hs row = (tm + 128h + 32i) - 128h
            #pragma unroll
            for (int j = 0; j < 4; j++) {
                float2 v = unpack2(acc2[4 * h + i][j]);
                int n = tn * 8 + 2 * j;
                hs[r][n]     = fmaxf(v.x + fbs[n],     0.f);
                hs[r][n + 1] = fmaxf(v.y + fbs[n + 1], 0.f);
            }
        }
        __syncthreads();

        if (tid < 128) {
            float a0 = pre_b[0], a1 = pre_b[1], a2 = pre_b[2], a3 = pre_b[3];
            const float* hr = hs[tid];
            #pragma unroll
            for (int c = 0; c < 64; c++) {
                float hv = hr[c];
                a0 = fmaf(hv, pws[c * 4 + 0], a0);
                a1 = fmaf(hv, pws[c * 4 + 1], a1);
                a2 = fmaf(hv, pws[c * 4 + 2], a2);
                a3 = fmaf(hv, pws[c * 4 + 3], a3);
            }
            // theta = (pi/2)*tanh(a); RY uses half angle -> (pi/4)*tanh(a)
            const float QP = 0.78539816339744831f;
            float c0, s0, c1, s1, c2, s2, c3, s3;
            sincosf(QP * tanhf(a0), &s0, &c0);
            sincosf(QP * tanhf(a1), &s1, &c1);
            sincosf(QP * tanhf(a2), &s2, &c2);
            sincosf(QP * tanhf(a3), &s3, &c3);

            float st[16];
            #pragma unroll
            for (int i = 0; i < 16; i++) st[i] = 0.25f;

            apply_ry(st, c0, s0, 8);
            apply_ry(st, c1, s1, 4);
            apply_ry(st, c2, s2, 2);
            apply_ry(st, c3, s3, 1);

            #pragma unroll
            for (int k = 0; k < 6; k++) {
                apply_cnot(st, 8, 4);   // CNOT(0,1)
                apply_cnot(st, 2, 1);   // CNOT(2,3)
                apply_cnot(st, 4, 2);   // CNOT(1,2)
                apply_ry(st, qc[4 * k + 0], qs[4 * k + 0], 8);
                apply_ry(st, qc[4 * k + 1], qs[4 * k + 1], 4);
                apply_ry(st, qc[4 * k + 2], qs[4 * k + 2], 2);
                apply_ry(st, qc[4 * k + 3], qs[4 * k + 3], 1);
            }

            float z0 = 0.f, z1 = 0.f, z2 = 0.f, z3 = 0.f;
            #pragma unroll
            for (int i = 0; i < 16; i++) {
                float p = st[i] * st[i];
                z0 += (i & 8) ? -p : p;
                z1 += (i & 4) ? -p : p;
                z2 += (i & 2) ? -p : p;
                z3 += (i & 1) ? -p : p;
            }
            float r = post_b[0];
            r = fmaf(z0, post_w[0], r);
            r = fmaf(z1, post_w[1], r);
            r = fmaf(z2, post_w[2], r);
            r = fmaf(z3, post_w[3], r);
            out[m0 + 128 * h + tid] = 1.f / (1.f + expf(-r));
        }
        __syncthreads();
    }
}

// ---------------------------------------------------------------------------
extern "C" void kernel_launch(void* const* d_in, const int* in_sizes, int n_in,
                              void* d_out, int out_size)
{
    const float* x      = (const float*)d_in[0];
    const float* w1     = (const float*)d_in[1];
    const float* b1     = (const float*)d_in[2];
    const float* w2     = (const float*)d_in[3];
    const float* b2     = (const float*)d_in[4];
    const float* fc_w   = (const float*)d_in[5];
    const float* fc_b   = (const float*)d_in[6];
    const float* pre_w  = (const float*)d_in[7];
    const float* pre_b  = (const float*)d_in[8];
    const float* q_par  = (const float*)d_in[9];
    const float* post_w = (const float*)d_in[10];
    const float* post_b = (const float*)d_in[11];
    float* out = (float*)d_out;

    conv_kernel<<<BATCH / 4, 256>>>(x, w1, b1, w2, b2);
    fc_quantum_kernel<<<BATCH / 256, 256>>>(fc_w, fc_b, pre_w, pre_b, q_par,
                                            post_w, post_b, out);
}